// round 8
// baseline (speedup 1.0000x reference)
#include <cuda_runtime.h>
#include <math.h>

#define NTOT    16384
#define TLEN    41
#define NSTEP   40
#define THREADS 640
#define PPB     128          // particles per block; 2 particles per thread
#define BLOCKS  128

// ---- smem float offsets ----
#define OFF_WIN  0            // [24k][80j]            1920
#define OFF_BIN  1920         // [80]
#define OFF_WH   2000         // [4l][80k][80j]        25600
#define OFF_BH   27600        // [4][80]
#define OFF_WOUT 27920        // [80k][24] (j padded: jh slice at 12*jh)
#define OFF_BOUT 29840        // [24]
#define OFF_U    29864        // [40][4]
#define OFF_Y    30024        // [20][128] particle state
#define OFF_FQ   32584        // [10][128] fq partials
#define OFF_A    33864        // [80][128] activations A
#define OFF_B    44104        // [80][128] activations B / output partials
#define SMEM_FLOATS 54344     // 217,376 B

typedef unsigned long long u64;

#define FMA2(d, a, b, c) \
    asm("fma.rn.f32x2 %0, %1, %2, %3;" : "=l"(d) : "l"(a), "l"(b), "l"(c))
#define PACK2(d, f) do { unsigned int _u = __float_as_uint(f); \
    asm("mov.b64 %0, {%1, %2};" : "=l"(d) : "r"(_u), "r"(_u)); } while (0)
#define UNPACK2(lo, hi, s) do { unsigned int _a, _b; \
    asm("mov.b64 {%0, %1}, %2;" : "=r"(_a), "=r"(_b) : "l"(s)); \
    lo = __uint_as_float(_a); hi = __uint_as_float(_b); } while (0)
#define TANHA(d, x) asm("tanh.approx.f32 %0, %1;" : "=f"(d) : "f"(x))

extern __shared__ float smem[];

__global__ void __launch_bounds__(THREADS, 1)
sde_kernel(const float* __restrict__ z, const float* __restrict__ t,
           const float* __restrict__ Tx, const float* __restrict__ noise,
           const float* __restrict__ tw_in, const float* __restrict__ tb_in,
           const float* __restrict__ tw_h,  const float* __restrict__ tb_h,
           const float* __restrict__ tw_out,const float* __restrict__ tb_out,
           const float* __restrict__ dw_in, const float* __restrict__ db_in,
           const float* __restrict__ dw_h,  const float* __restrict__ db_h,
           const float* __restrict__ dw_out,const float* __restrict__ db_out,
           float* __restrict__ ys, float* __restrict__ lqout) {
    float* s_win  = smem + OFF_WIN;
    float* s_bin  = smem + OFF_BIN;
    float* s_wh   = smem + OFF_WH;
    float* s_bh   = smem + OFF_BH;
    float* s_wout = smem + OFF_WOUT;
    float* s_bout = smem + OFF_BOUT;
    float* s_u    = smem + OFF_U;
    float* s_y    = smem + OFF_Y;
    float* s_fq   = smem + OFF_FQ;
    float* s_A    = smem + OFF_A;
    float* s_B    = smem + OFF_B;

    const int tid  = threadIdx.x;
    const int jg   = tid >> 6;      // j-group 0..9 (warp-uniform)
    const int pair = tid & 63;      // particle pair 0..63
    const int col0 = 2 * pair;      // smem column of particle 0
    const int jb   = 8 * jg;        // MLP j-slice [jb, jb+8)
    const int d0   = 2 * jg;        // owned state dims [d0, d0+2)
    // output layer roles (groups 0..7): k in [20kh,20kh+20), j in [10jh,10jh+10)
    const int kh   = jg >> 1;
    const int jh   = jg & 1;

    // ---- cooperative load + transpose of drift weights into smem ----
    for (int idx = tid; idx < 24 * 80; idx += THREADS) {
        int j = idx / 24, k = idx % 24;
        s_win[k * 80 + j] = dw_in[idx];
    }
    for (int idx = tid; idx < 4 * 6400; idx += THREADS) {
        int l = idx / 6400, r = idx % 6400, j = r / 80, k = r % 80;
        s_wh[l * 6400 + k * 80 + j] = dw_h[idx];
    }
    for (int idx = tid; idx < 20 * 80; idx += THREADS) {
        int j = idx / 80, k = idx % 80;
        s_wout[k * 24 + 12 * (j / 10) + (j % 10)] = dw_out[idx];
    }
    for (int idx = tid; idx < 80;  idx += THREADS) s_bin[idx]  = db_in[idx];
    for (int idx = tid; idx < 320; idx += THREADS) s_bh[idx]   = db_h[idx];
    for (int idx = tid; idx < 20;  idx += THREADS) s_bout[idx] = db_out[idx];

    // ---- t-MLP fused: threads [192,232) compute u(t_i) -> s_u ----
    if (tid >= 192 && tid < 192 + NSTEP) {
        int i = tid - 192;
        float ti = t[i];
        float h[20], h2[20];
#pragma unroll
        for (int j = 0; j < 20; j++) h[j] = fmaxf(tw_in[j] * ti + tb_in[j], 0.f);
        for (int l = 0; l < 4; l++) {
            const float* w = tw_h + l * 400;
            const float* b = tb_h + l * 20;
#pragma unroll
            for (int j = 0; j < 20; j++) {
                float a = b[j];
#pragma unroll
                for (int k = 0; k < 20; k++) a += w[j * 20 + k] * h[k];
                h2[j] = fmaxf(a, 0.f);
            }
#pragma unroll
            for (int j = 0; j < 20; j++) h[j] = h2[j];
        }
#pragma unroll
        for (int c = 0; c < 4; c++) {
            float a = tb_out[c];
#pragma unroll
            for (int k = 0; k < 20; k++) a += tw_out[c * 20 + k] * h[k];
            s_u[i * 4 + c] = a;
        }
    }

    const int n0 = blockIdx.x * PPB + col0;   // particle 0; particle 1 = n0+1
    const float Tval = Tx[n0 >> 6];           // same for both (n0 even)
    const float dt  = t[1] - t[0];
    const float sdt = sqrtf(dt);

    // ---- init: own dims of both particles ----
    float y0[2], y1[2];
#pragma unroll
    for (int i = 0; i < 2; i++) {
        y0[i] = z[(size_t)n0 * 20 + d0 + i];
        y1[i] = z[(size_t)(n0 + 1) * 20 + d0 + i];
        *(float2*)(s_y + (d0 + i) * 128 + col0) = make_float2(y0[i], y1[i]);
        ys[(size_t)n0 * 20 + d0 + i]       = y0[i];
        ys[(size_t)(n0 + 1) * 20 + d0 + i] = y1[i];
    }
    float lq0 = 0.f, lq1 = 0.f;
    if (jg == 0) {
        if (n0 >= 40 && (n0 - 40) % 41 == 0) lqout[(n0 - 40) / 41] = 0.f;
        int n1 = n0 + 1;
        if (n1 >= 40 && (n1 - 40) % 41 == 0) lqout[(n1 - 40) / 41] = 0.f;
    }
    __syncthreads();

    for (int step = 0; step < NSTEP; step++) {
        float ut[4];
#pragma unroll
        for (int c = 0; c < 4; c++) ut[c] = s_u[step * 4 + c] * Tval;

        // ======== input layer: [y(20), ut(4)] -> j in [jb, jb+8), relu =====
        {
            u64 a0[4], a1[4];
            {
                const ulonglong2* bv = (const ulonglong2*)(s_bin + jb);
                ulonglong2 b0 = bv[0], b1 = bv[1];
                a0[0] = b0.x; a0[1] = b0.y; a0[2] = b1.x; a0[3] = b1.y;
                a1[0] = b0.x; a1[1] = b0.y; a1[2] = b1.x; a1[3] = b1.y;
            }
#pragma unroll 5
            for (int k = 0; k < 20; k++) {
                float2 yk = *(const float2*)(s_y + k * 128 + col0);
                u64 x0, x1; PACK2(x0, yk.x); PACK2(x1, yk.y);
                const ulonglong2* w = (const ulonglong2*)(s_win + k * 80 + jb);
                ulonglong2 w0 = w[0], w1 = w[1];
                FMA2(a0[0], w0.x, x0, a0[0]); FMA2(a0[1], w0.y, x0, a0[1]);
                FMA2(a0[2], w1.x, x0, a0[2]); FMA2(a0[3], w1.y, x0, a0[3]);
                FMA2(a1[0], w0.x, x1, a1[0]); FMA2(a1[1], w0.y, x1, a1[1]);
                FMA2(a1[2], w1.x, x1, a1[2]); FMA2(a1[3], w1.y, x1, a1[3]);
            }
#pragma unroll
            for (int k = 20; k < 24; k++) {     // ut same for both particles
                u64 xu; PACK2(xu, ut[k - 20]);
                const ulonglong2* w = (const ulonglong2*)(s_win + k * 80 + jb);
                ulonglong2 w0 = w[0], w1 = w[1];
                FMA2(a0[0], w0.x, xu, a0[0]); FMA2(a0[1], w0.y, xu, a0[1]);
                FMA2(a0[2], w1.x, xu, a0[2]); FMA2(a0[3], w1.y, xu, a0[3]);
                FMA2(a1[0], w0.x, xu, a1[0]); FMA2(a1[1], w0.y, xu, a1[1]);
                FMA2(a1[2], w1.x, xu, a1[2]); FMA2(a1[3], w1.y, xu, a1[3]);
            }
            float* hw = s_A + jb * 128 + col0;
#pragma unroll
            for (int q = 0; q < 4; q++) {
                float p0a, p0b, p1a, p1b;
                UNPACK2(p0a, p0b, a0[q]);
                UNPACK2(p1a, p1b, a1[q]);
                *(float2*)(hw + (2*q)   * 128) = make_float2(fmaxf(p0a, 0.f), fmaxf(p1a, 0.f));
                *(float2*)(hw + (2*q+1) * 128) = make_float2(fmaxf(p0b, 0.f), fmaxf(p1b, 0.f));
            }
        }
        __syncthreads();

        // ======== 4 hidden layers 80 -> 80, tanh.approx ========
        float* hin  = s_A;
        float* hout = s_B;
        for (int l = 0; l < 4; l++) {
            const float* wl = s_wh + l * 6400 + jb;
            u64 a0[4], a1[4];
            {
                const ulonglong2* bv = (const ulonglong2*)(s_bh + l * 80 + jb);
                ulonglong2 b0 = bv[0], b1 = bv[1];
                a0[0] = b0.x; a0[1] = b0.y; a0[2] = b1.x; a0[3] = b1.y;
                a1[0] = b0.x; a1[1] = b0.y; a1[2] = b1.x; a1[3] = b1.y;
            }
#pragma unroll 10
            for (int k = 0; k < 80; k++) {
                float2 hk = *(const float2*)(hin + k * 128 + col0);
                u64 x0, x1; PACK2(x0, hk.x); PACK2(x1, hk.y);
                const ulonglong2* w = (const ulonglong2*)(wl + k * 80);
                ulonglong2 w0 = w[0], w1 = w[1];
                FMA2(a0[0], w0.x, x0, a0[0]); FMA2(a0[1], w0.y, x0, a0[1]);
                FMA2(a0[2], w1.x, x0, a0[2]); FMA2(a0[3], w1.y, x0, a0[3]);
                FMA2(a1[0], w0.x, x1, a1[0]); FMA2(a1[1], w0.y, x1, a1[1]);
                FMA2(a1[2], w1.x, x1, a1[2]); FMA2(a1[3], w1.y, x1, a1[3]);
            }
            float* hw = hout + jb * 128 + col0;
#pragma unroll
            for (int q = 0; q < 4; q++) {
                float p0a, p0b, p1a, p1b;
                UNPACK2(p0a, p0b, a0[q]);
                UNPACK2(p1a, p1b, a1[q]);
                TANHA(p0a, p0a); TANHA(p0b, p0b);
                TANHA(p1a, p1a); TANHA(p1b, p1b);
                *(float2*)(hw + (2*q)   * 128) = make_float2(p0a, p1a);
                *(float2*)(hw + (2*q+1) * 128) = make_float2(p0b, p1b);
            }
            __syncthreads();
            float* tmp = hin; hin = hout; hout = tmp;
        }
        // after 4 swaps: hin == s_A (final hidden), hout == s_B (free)

        // ---- prefetch noise (own 2 dims x 2 particles) ----
        float2 nz0, nz1;
        {
            const float* np0 = noise + ((size_t)step * NTOT + n0) * 22 + d0;
            nz0 = *(const float2*)np0;
            nz1 = *(const float2*)(np0 + 22);
        }

        // ======== output layer (groups 0..7): k in [20kh,+20), j in [10jh,+10)
        if (jg < 8) {
            u64 o0[5], o1[5];
#pragma unroll
            for (int q = 0; q < 5; q++) { o0[q] = 0ull; o1[q] = 0ull; }
            const float* hr = hin + (20 * kh) * 128 + col0;
            const float* wr = s_wout + (20 * kh) * 24 + 12 * jh;
#pragma unroll 10
            for (int kk = 0; kk < 20; kk++) {
                float2 hk = *(const float2*)(hr + kk * 128);
                u64 x0, x1; PACK2(x0, hk.x); PACK2(x1, hk.y);
                const float* w = wr + kk * 24;
                // j-slice lanes (verified alignment): w[0..3] 16B-aligned v2.u64,
                // then u64 at +4 (j4,5), +6 (j6,7), +8 (j8,9) — all 8B-aligned.
                ulonglong2 w01 = *(const ulonglong2*)w;      // j0..3
                u64 w2 = *(const u64*)(w + 4);               // j4,5
                u64 w3 = *(const u64*)(w + 6);               // j6,7
                u64 w4 = *(const u64*)(w + 8);               // j8,9
                FMA2(o0[0], w01.x, x0, o0[0]); FMA2(o0[1], w01.y, x0, o0[1]);
                FMA2(o0[2], w2,    x0, o0[2]); FMA2(o0[3], w3,    x0, o0[3]);
                FMA2(o0[4], w4,    x0, o0[4]);
                FMA2(o1[0], w01.x, x1, o1[0]); FMA2(o1[1], w01.y, x1, o1[1]);
                FMA2(o1[2], w2,    x1, o1[2]); FMA2(o1[3], w3,    x1, o1[3]);
                FMA2(o1[4], w4,    x1, o1[4]);
            }
            // partial rows = 20*kh + 10*jh + jj (jj = 0..9)
            float* pw = hout + (20 * kh + 10 * jh) * 128 + col0;
#pragma unroll
            for (int q = 0; q < 5; q++) {
                float p0a, p0b, p1a, p1b;
                UNPACK2(p0a, p0b, o0[q]);
                UNPACK2(p1a, p1b, o1[q]);
                *(float2*)(pw + (2*q)   * 128) = make_float2(p0a, p1a);
                *(float2*)(pw + (2*q+1) * 128) = make_float2(p0b, p1b);
            }
        }
        __syncthreads();

        // ======== reduce partials + SDE update (all groups, dims [d0,d0+2))
        // h = -y ; f = o + y ; uu = 2(o + 2y) ; f_logqp = 2*sum((o+2y)^2)
        {
            float fq0 = 0.f, fq1 = 0.f;
            float yn0[2], yn1[2];
#pragma unroll
            for (int i = 0; i < 2; i++) {
                int d = d0 + i;
                float s0 = s_bout[d], s1 = s0;
#pragma unroll
                for (int g = 0; g < 4; g++) {
                    float2 p = *(const float2*)(hout + (g * 20 + d) * 128 + col0);
                    s0 += p.x; s1 += p.y;
                }
                float f0 = s0 + y0[i], uu0 = s0 + 2.f * y0[i];
                float f1 = s1 + y1[i], uu1 = s1 + 2.f * y1[i];
                fq0 += uu0 * uu0; fq1 += uu1 * uu1;
                float nzi0 = (i == 0) ? nz0.x : nz0.y;
                float nzi1 = (i == 0) ? nz1.x : nz1.y;
                yn0[i] = y0[i] + f0 * dt + 0.5f * nzi0 * sdt;  // SIGMA = 0.5
                yn1[i] = y1[i] + f1 * dt + 0.5f * nzi1 * sdt;
                y0[i] = yn0[i]; y1[i] = yn1[i];
                *(float2*)(s_y + d * 128 + col0) = make_float2(yn0[i], yn1[i]);
            }
            float* ywp0 = ys + ((size_t)(step + 1) * NTOT + n0) * 20 + d0;
            *(float2*)ywp0        = make_float2(yn0[0], yn0[1]);
            *(float2*)(ywp0 + 20) = make_float2(yn1[0], yn1[1]);
            *(float2*)(s_fq + jg * 128 + col0) = make_float2(fq0, fq1);
        }
        __syncthreads();

        // jg0 owns logqp bookkeeping
        if (jg == 0) {
            float f0t = 0.f, f1t = 0.f;
#pragma unroll
            for (int g = 0; g < 10; g++) {
                float2 p = *(const float2*)(s_fq + g * 128 + col0);
                f0t += p.x; f1t += p.y;
            }
            lq0 += 2.f * f0t * dt;
            lq1 += 2.f * f1t * dt;
            size_t idx0 = (size_t)(step + 1) * NTOT + n0;
            size_t r0 = idx0 - 40;
            if (r0 % 41 == 0) lqout[r0 / 41] = lq0;
            size_t r1 = idx0 + 1 - 40;
            if (r1 % 41 == 0) lqout[r1 / 41] = lq1;
        }
    }
}

// ---------------------------------------------------------------------------
extern "C" void kernel_launch(void* const* d_in, const int* in_sizes, int n_in,
                              void* d_out, int out_size) {
    const float* z      = (const float*)d_in[0];
    const float* t      = (const float*)d_in[1];
    const float* Tx     = (const float*)d_in[2];
    const float* noise  = (const float*)d_in[3];
    const float* tw_in  = (const float*)d_in[4];
    const float* tb_in  = (const float*)d_in[5];
    const float* tw_h   = (const float*)d_in[6];
    const float* tb_h   = (const float*)d_in[7];
    const float* tw_out = (const float*)d_in[8];
    const float* tb_out = (const float*)d_in[9];
    const float* dw_in  = (const float*)d_in[10];
    const float* db_in  = (const float*)d_in[11];
    const float* dw_h   = (const float*)d_in[12];
    const float* db_h   = (const float*)d_in[13];
    const float* dw_out = (const float*)d_in[14];
    const float* db_out = (const float*)d_in[15];

    float* ys    = (float*)d_out;
    float* lqout = ys + (size_t)TLEN * NTOT * 20;

    const size_t smem_bytes = (size_t)SMEM_FLOATS * sizeof(float); // ~217 KB
    cudaFuncSetAttribute(sde_kernel, cudaFuncAttributeMaxDynamicSharedMemorySize,
                         (int)smem_bytes);

    sde_kernel<<<BLOCKS, THREADS, smem_bytes>>>(z, t, Tx, noise,
                                                tw_in, tb_in, tw_h, tb_h,
                                                tw_out, tb_out,
                                                dw_in, db_in, dw_h, db_h,
                                                dw_out, db_out, ys, lqout);
}

// round 9
// speedup vs baseline: 1.0106x; 1.0106x over previous
#include <cuda_runtime.h>
#include <math.h>

#define NTOT    16384
#define TLEN    41
#define NSTEP   40
#define THREADS 128
#define PPB     128          // particles per block; 4 particles per thread
#define BLOCKS  128

// ---- smem float offsets ----
#define OFF_WIN  0            // [24k][80j]
#define OFF_BIN  1920         // [80]
#define OFF_WH   2000         // [4l][80k][80j]
#define OFF_BH   27600        // [4][80]
#define OFF_WOUT 27920        // [80k][20j]
#define OFF_BOUT 29520        // [20]
#define OFF_U    29540        // [40][4]
#define OFF_Y    29700        // [20][128] particle state
#define OFF_FQ   32260        // [4][128] fq partials
#define OFF_A    32772        // [80][128] activations A
#define OFF_B    43012        // [80][128] activations B / output partials
#define SMEM_FLOATS 53252     // 213,008 B

typedef unsigned long long u64;

#define FMA2(d, a, b, c) \
    asm("fma.rn.f32x2 %0, %1, %2, %3;" : "=l"(d) : "l"(a), "l"(b), "l"(c))
#define PACK2(d, f) do { unsigned int _u = __float_as_uint(f); \
    asm("mov.b64 %0, {%1, %2};" : "=l"(d) : "r"(_u), "r"(_u)); } while (0)
#define UNPACK2(lo, hi, s) do { unsigned int _a, _b; \
    asm("mov.b64 {%0, %1}, %2;" : "=r"(_a), "=r"(_b) : "l"(s)); \
    lo = __uint_as_float(_a); hi = __uint_as_float(_b); } while (0)
#define TANHA(d, x) asm("tanh.approx.f32 %0, %1;" : "=f"(d) : "f"(x))

extern __shared__ float smem[];

__global__ void __launch_bounds__(THREADS, 1)
sde_kernel(const float* __restrict__ z, const float* __restrict__ t,
           const float* __restrict__ Tx, const float* __restrict__ noise,
           const float* __restrict__ tw_in, const float* __restrict__ tb_in,
           const float* __restrict__ tw_h,  const float* __restrict__ tb_h,
           const float* __restrict__ tw_out,const float* __restrict__ tb_out,
           const float* __restrict__ dw_in, const float* __restrict__ db_in,
           const float* __restrict__ dw_h,  const float* __restrict__ db_h,
           const float* __restrict__ dw_out,const float* __restrict__ db_out,
           float* __restrict__ ys, float* __restrict__ lqout) {
    float* s_win  = smem + OFF_WIN;
    float* s_bin  = smem + OFF_BIN;
    float* s_wh   = smem + OFF_WH;
    float* s_bh   = smem + OFF_BH;
    float* s_wout = smem + OFF_WOUT;
    float* s_bout = smem + OFF_BOUT;
    float* s_u    = smem + OFF_U;
    float* s_y    = smem + OFF_Y;
    float* s_fq   = smem + OFF_FQ;
    float* s_A    = smem + OFF_A;
    float* s_B    = smem + OFF_B;

    const int tid  = threadIdx.x;
    const int jg   = tid >> 5;      // j-group 0..3 (== warp id, warp-uniform)
    const int quad = tid & 31;      // particle quad 0..31
    const int col0 = 4 * quad;      // smem column of particle 0 (16B aligned)
    const int jb   = 20 * jg;       // MLP j-slice [jb, jb+20)
    const int d0   = 5 * jg;        // owned state dims [d0, d0+5)

    // ---- cooperative load + transpose of drift weights into smem ----
    for (int idx = tid; idx < 24 * 80; idx += THREADS) {
        int j = idx / 24, k = idx % 24;
        s_win[k * 80 + j] = dw_in[idx];
    }
    for (int idx = tid; idx < 4 * 6400; idx += THREADS) {
        int l = idx / 6400, r = idx % 6400, j = r / 80, k = r % 80;
        s_wh[l * 6400 + k * 80 + j] = dw_h[idx];
    }
    for (int idx = tid; idx < 20 * 80; idx += THREADS) {
        int j = idx / 80, k = idx % 80;
        s_wout[k * 20 + j] = dw_out[idx];
    }
    for (int idx = tid; idx < 80;  idx += THREADS) s_bin[idx]  = db_in[idx];
    for (int idx = tid; idx < 320; idx += THREADS) s_bh[idx]   = db_h[idx];
    for (int idx = tid; idx < 20;  idx += THREADS) s_bout[idx] = db_out[idx];

    // ---- t-MLP fused: threads [0,40) compute u(t_i) -> s_u ----
    if (tid < NSTEP) {
        float ti = t[tid];
        float h[20], h2[20];
#pragma unroll
        for (int j = 0; j < 20; j++) h[j] = fmaxf(tw_in[j] * ti + tb_in[j], 0.f);
        for (int l = 0; l < 4; l++) {
            const float* w = tw_h + l * 400;
            const float* b = tb_h + l * 20;
#pragma unroll
            for (int j = 0; j < 20; j++) {
                float a = b[j];
#pragma unroll
                for (int k = 0; k < 20; k++) a += w[j * 20 + k] * h[k];
                h2[j] = fmaxf(a, 0.f);
            }
#pragma unroll
            for (int j = 0; j < 20; j++) h[j] = h2[j];
        }
#pragma unroll
        for (int c = 0; c < 4; c++) {
            float a = tb_out[c];
#pragma unroll
            for (int k = 0; k < 20; k++) a += tw_out[c * 20 + k] * h[k];
            s_u[tid * 4 + c] = a;
        }
    }

    const int n0 = blockIdx.x * PPB + col0;   // particles n0..n0+3
    const float Tval = Tx[n0 >> 6];           // same for all 4 (col0 % 4 == 0)
    const float dt  = t[1] - t[0];
    const float sdt = sqrtf(dt);

    // ---- init: own dims [d0,d0+5) of 4 particles ----
    float yo[4][5];
#pragma unroll
    for (int p = 0; p < 4; p++)
#pragma unroll
        for (int i = 0; i < 5; i++) {
            yo[p][i] = z[(size_t)(n0 + p) * 20 + d0 + i];
            ys[(size_t)(n0 + p) * 20 + d0 + i] = yo[p][i];
        }
#pragma unroll
    for (int i = 0; i < 5; i++)
        *(float4*)(s_y + (d0 + i) * 128 + col0) =
            make_float4(yo[0][i], yo[1][i], yo[2][i], yo[3][i]);
    float lq[4] = {0.f, 0.f, 0.f, 0.f};
    if (jg == 0) {
#pragma unroll
        for (int p = 0; p < 4; p++) {
            int np = n0 + p;
            if (np >= 40 && (np - 40) % 41 == 0) lqout[(np - 40) / 41] = 0.f;
        }
    }
    __syncthreads();

    for (int step = 0; step < NSTEP; step++) {
        float ut[4];
#pragma unroll
        for (int c = 0; c < 4; c++) ut[c] = s_u[step * 4 + c] * Tval;

        // ======== input layer: [y(20), ut(4)] -> j in [jb,jb+20), relu =====
        {
            u64 acc[4][10];
            {
                const ulonglong2* bv = (const ulonglong2*)(s_bin + jb);
#pragma unroll
                for (int q5 = 0; q5 < 5; q5++) {
                    ulonglong2 b = bv[q5];
#pragma unroll
                    for (int p = 0; p < 4; p++) {
                        acc[p][2*q5] = b.x; acc[p][2*q5+1] = b.y;
                    }
                }
            }
#pragma unroll 4
            for (int k = 0; k < 20; k++) {
                float4 yk = *(const float4*)(s_y + k * 128 + col0);
                u64 x0, x1, x2, x3;
                PACK2(x0, yk.x); PACK2(x1, yk.y); PACK2(x2, yk.z); PACK2(x3, yk.w);
                const ulonglong2* w = (const ulonglong2*)(s_win + k * 80 + jb);
#pragma unroll
                for (int q5 = 0; q5 < 5; q5++) {
                    ulonglong2 wv = w[q5];
                    FMA2(acc[0][2*q5], wv.x, x0, acc[0][2*q5]); FMA2(acc[0][2*q5+1], wv.y, x0, acc[0][2*q5+1]);
                    FMA2(acc[1][2*q5], wv.x, x1, acc[1][2*q5]); FMA2(acc[1][2*q5+1], wv.y, x1, acc[1][2*q5+1]);
                    FMA2(acc[2][2*q5], wv.x, x2, acc[2][2*q5]); FMA2(acc[2][2*q5+1], wv.y, x2, acc[2][2*q5+1]);
                    FMA2(acc[3][2*q5], wv.x, x3, acc[3][2*q5]); FMA2(acc[3][2*q5+1], wv.y, x3, acc[3][2*q5+1]);
                }
            }
#pragma unroll
            for (int k = 20; k < 24; k++) {   // ut identical for the 4 particles
                u64 xu; PACK2(xu, ut[k - 20]);
                const ulonglong2* w = (const ulonglong2*)(s_win + k * 80 + jb);
#pragma unroll
                for (int q5 = 0; q5 < 5; q5++) {
                    ulonglong2 wv = w[q5];
                    FMA2(acc[0][2*q5], wv.x, xu, acc[0][2*q5]); FMA2(acc[0][2*q5+1], wv.y, xu, acc[0][2*q5+1]);
                    FMA2(acc[1][2*q5], wv.x, xu, acc[1][2*q5]); FMA2(acc[1][2*q5+1], wv.y, xu, acc[1][2*q5+1]);
                    FMA2(acc[2][2*q5], wv.x, xu, acc[2][2*q5]); FMA2(acc[2][2*q5+1], wv.y, xu, acc[2][2*q5+1]);
                    FMA2(acc[3][2*q5], wv.x, xu, acc[3][2*q5]); FMA2(acc[3][2*q5+1], wv.y, xu, acc[3][2*q5+1]);
                }
            }
            float* hw = s_A + jb * 128 + col0;
#pragma unroll
            for (int q = 0; q < 10; q++) {
                float a0,b0,a1,b1,a2,b2,a3,b3;
                UNPACK2(a0,b0,acc[0][q]); UNPACK2(a1,b1,acc[1][q]);
                UNPACK2(a2,b2,acc[2][q]); UNPACK2(a3,b3,acc[3][q]);
                *(float4*)(hw + (2*q)   * 128) = make_float4(fmaxf(a0,0.f), fmaxf(a1,0.f), fmaxf(a2,0.f), fmaxf(a3,0.f));
                *(float4*)(hw + (2*q+1) * 128) = make_float4(fmaxf(b0,0.f), fmaxf(b1,0.f), fmaxf(b2,0.f), fmaxf(b3,0.f));
            }
        }
        __syncthreads();

        // ======== 4 hidden layers 80 -> 80, tanh.approx ========
        float* hin  = s_A;
        float* hout = s_B;
        for (int l = 0; l < 4; l++) {
            const float* wl = s_wh + l * 6400 + jb;
            u64 acc[4][10];
            {
                const ulonglong2* bv = (const ulonglong2*)(s_bh + l * 80 + jb);
#pragma unroll
                for (int q5 = 0; q5 < 5; q5++) {
                    ulonglong2 b = bv[q5];
#pragma unroll
                    for (int p = 0; p < 4; p++) {
                        acc[p][2*q5] = b.x; acc[p][2*q5+1] = b.y;
                    }
                }
            }
#pragma unroll 4
            for (int k = 0; k < 80; k++) {
                float4 hk = *(const float4*)(hin + k * 128 + col0);
                u64 x0, x1, x2, x3;
                PACK2(x0, hk.x); PACK2(x1, hk.y); PACK2(x2, hk.z); PACK2(x3, hk.w);
                const ulonglong2* w = (const ulonglong2*)(wl + k * 80);
#pragma unroll
                for (int q5 = 0; q5 < 5; q5++) {
                    ulonglong2 wv = w[q5];
                    FMA2(acc[0][2*q5], wv.x, x0, acc[0][2*q5]); FMA2(acc[0][2*q5+1], wv.y, x0, acc[0][2*q5+1]);
                    FMA2(acc[1][2*q5], wv.x, x1, acc[1][2*q5]); FMA2(acc[1][2*q5+1], wv.y, x1, acc[1][2*q5+1]);
                    FMA2(acc[2][2*q5], wv.x, x2, acc[2][2*q5]); FMA2(acc[2][2*q5+1], wv.y, x2, acc[2][2*q5+1]);
                    FMA2(acc[3][2*q5], wv.x, x3, acc[3][2*q5]); FMA2(acc[3][2*q5+1], wv.y, x3, acc[3][2*q5+1]);
                }
            }
            float* hw = hout + jb * 128 + col0;
#pragma unroll
            for (int q = 0; q < 10; q++) {
                float a0,b0,a1,b1,a2,b2,a3,b3;
                UNPACK2(a0,b0,acc[0][q]); UNPACK2(a1,b1,acc[1][q]);
                UNPACK2(a2,b2,acc[2][q]); UNPACK2(a3,b3,acc[3][q]);
                TANHA(a0,a0); TANHA(a1,a1); TANHA(a2,a2); TANHA(a3,a3);
                TANHA(b0,b0); TANHA(b1,b1); TANHA(b2,b2); TANHA(b3,b3);
                *(float4*)(hw + (2*q)   * 128) = make_float4(a0,a1,a2,a3);
                *(float4*)(hw + (2*q+1) * 128) = make_float4(b0,b1,b2,b3);
            }
            __syncthreads();
            float* tmp = hin; hin = hout; hout = tmp;
        }
        // after 4 swaps: hin == s_A (final hidden), hout == s_B (free)

        // ---- prefetch noise (own 5 dims x 4 particles) ----
        float nz[4][5];
#pragma unroll
        for (int p = 0; p < 4; p++) {
            const float* np_ = noise + ((size_t)step * NTOT + n0 + p) * 22 + d0;
#pragma unroll
            for (int i = 0; i < 5; i++) nz[p][i] = np_[i];
        }

        // ======== output layer: k in [jb,jb+20), all 20 j (partials) ======
        {
            u64 oc[4][10];
#pragma unroll
            for (int p = 0; p < 4; p++)
#pragma unroll
                for (int q = 0; q < 10; q++) oc[p][q] = 0ull;
            const float* hr = hin + jb * 128 + col0;
#pragma unroll 4
            for (int kk = 0; kk < 20; kk++) {
                float4 hk = *(const float4*)(hr + kk * 128);
                u64 x0, x1, x2, x3;
                PACK2(x0, hk.x); PACK2(x1, hk.y); PACK2(x2, hk.z); PACK2(x3, hk.w);
                const ulonglong2* w = (const ulonglong2*)(s_wout + (jb + kk) * 20);
#pragma unroll
                for (int q5 = 0; q5 < 5; q5++) {
                    ulonglong2 wv = w[q5];
                    FMA2(oc[0][2*q5], wv.x, x0, oc[0][2*q5]); FMA2(oc[0][2*q5+1], wv.y, x0, oc[0][2*q5+1]);
                    FMA2(oc[1][2*q5], wv.x, x1, oc[1][2*q5]); FMA2(oc[1][2*q5+1], wv.y, x1, oc[1][2*q5+1]);
                    FMA2(oc[2][2*q5], wv.x, x2, oc[2][2*q5]); FMA2(oc[2][2*q5+1], wv.y, x2, oc[2][2*q5+1]);
                    FMA2(oc[3][2*q5], wv.x, x3, oc[3][2*q5]); FMA2(oc[3][2*q5+1], wv.y, x3, oc[3][2*q5+1]);
                }
            }
            // partial rows = jg*20 + j
            float* pw = hout + (jg * 20) * 128 + col0;
#pragma unroll
            for (int q = 0; q < 10; q++) {
                float a0,b0,a1,b1,a2,b2,a3,b3;
                UNPACK2(a0,b0,oc[0][q]); UNPACK2(a1,b1,oc[1][q]);
                UNPACK2(a2,b2,oc[2][q]); UNPACK2(a3,b3,oc[3][q]);
                *(float4*)(pw + (2*q)   * 128) = make_float4(a0,a1,a2,a3);
                *(float4*)(pw + (2*q+1) * 128) = make_float4(b0,b1,b2,b3);
            }
        }
        __syncthreads();

        // ======== reduce partials + SDE update (own dims [d0,d0+5)) =======
        // h = -y ; f = o + y ; uu = 2(o + 2y) ; f_logqp = 2*sum((o+2y)^2)
        {
            float fq[4] = {0.f, 0.f, 0.f, 0.f};
#pragma unroll
            for (int i = 0; i < 5; i++) {
                int d = d0 + i;
                float bo = s_bout[d];
                float s0 = bo, s1 = bo, s2 = bo, s3 = bo;
#pragma unroll
                for (int g = 0; g < 4; g++) {
                    float4 p = *(const float4*)(hout + (g * 20 + d) * 128 + col0);
                    s0 += p.x; s1 += p.y; s2 += p.z; s3 += p.w;
                }
                float sv[4] = {s0, s1, s2, s3};
#pragma unroll
                for (int p = 0; p < 4; p++) {
                    float f  = sv[p] + yo[p][i];
                    float uu = sv[p] + 2.f * yo[p][i];
                    fq[p] += uu * uu;
                    yo[p][i] = yo[p][i] + f * dt + 0.5f * nz[p][i] * sdt; // SIGMA=0.5
                    ys[((size_t)(step + 1) * NTOT + n0 + p) * 20 + d] = yo[p][i];
                }
                *(float4*)(s_y + d * 128 + col0) =
                    make_float4(yo[0][i], yo[1][i], yo[2][i], yo[3][i]);
            }
            *(float4*)(s_fq + jg * 128 + col0) =
                make_float4(fq[0], fq[1], fq[2], fq[3]);
        }
        __syncthreads();

        // jg0 owns logqp bookkeeping (s_fq stable until next step's reduce)
        if (jg == 0) {
            float ft[4] = {0.f, 0.f, 0.f, 0.f};
#pragma unroll
            for (int g = 0; g < 4; g++) {
                float4 v = *(const float4*)(s_fq + g * 128 + col0);
                ft[0] += v.x; ft[1] += v.y; ft[2] += v.z; ft[3] += v.w;
            }
#pragma unroll
            for (int p = 0; p < 4; p++) {
                lq[p] += 2.f * ft[p] * dt;
                size_t idx = (size_t)(step + 1) * NTOT + n0 + p;
                size_t r = idx - 40;
                if (r % 41 == 0) lqout[r / 41] = lq[p];
            }
        }
    }
}

// ---------------------------------------------------------------------------
extern "C" void kernel_launch(void* const* d_in, const int* in_sizes, int n_in,
                              void* d_out, int out_size) {
    const float* z      = (const float*)d_in[0];
    const float* t      = (const float*)d_in[1];
    const float* Tx     = (const float*)d_in[2];
    const float* noise  = (const float*)d_in[3];
    const float* tw_in  = (const float*)d_in[4];
    const float* tb_in  = (const float*)d_in[5];
    const float* tw_h   = (const float*)d_in[6];
    const float* tb_h   = (const float*)d_in[7];
    const float* tw_out = (const float*)d_in[8];
    const float* tb_out = (const float*)d_in[9];
    const float* dw_in  = (const float*)d_in[10];
    const float* db_in  = (const float*)d_in[11];
    const float* dw_h   = (const float*)d_in[12];
    const float* db_h   = (const float*)d_in[13];
    const float* dw_out = (const float*)d_in[14];
    const float* db_out = (const float*)d_in[15];

    float* ys    = (float*)d_out;
    float* lqout = ys + (size_t)TLEN * NTOT * 20;

    const size_t smem_bytes = (size_t)SMEM_FLOATS * sizeof(float); // ~213 KB
    cudaFuncSetAttribute(sde_kernel, cudaFuncAttributeMaxDynamicSharedMemorySize,
                         (int)smem_bytes);

    sde_kernel<<<BLOCKS, THREADS, smem_bytes>>>(z, t, Tx, noise,
                                                tw_in, tb_in, tw_h, tb_h,
                                                tw_out, tb_out,
                                                dw_in, db_in, dw_h, db_h,
                                                dw_out, db_out, ys, lqout);
}